// round 1
// baseline (speedup 1.0000x reference)
#include <cuda_runtime.h>
#include <cuda_bf16.h>
#include <math.h>
#include <stdint.h>

// Problem dims
#define MDIM  16384
#define KDIM  784
#define NDIM  8192
#define CDIM  10
#define NK1   (NDIM * KDIM)        // 6,422,528
#define NK2   (CDIM * NDIM)        // 81,920
#define J1    3211264u             // int(0.5 * NK1)
#define J2    40960u               // int(0.5 * NK2)

#define BM 128
#define BN 128
#define BKT 16
#define LDT 20                     // padded smem stride (conflict-free frag loads)
#define NTILES (NDIM / BN)         // 64

// ---------------- scratch (device globals; no allocation allowed) ----------------
__device__ float    g_xt[MDIM * KDIM];          // tf32-rounded x
__device__ float    g_w1m[NDIM * KDIM];         // masked+tf32 w1
__device__ float    g_w2m[CDIM * NDIM];         // masked w2 (fp32)
__device__ float    g_part[NTILES * MDIM * CDIM]; // partial logits per N-tile
__device__ unsigned g_hist[256];
__device__ unsigned g_prefix;
__device__ unsigned g_rank;
__device__ unsigned g_nLess;
__device__ unsigned g_nTie;
__device__ unsigned g_T[2];
__device__ unsigned g_cutoff[2];
__device__ unsigned g_tieIdx[8192];

__device__ __forceinline__ unsigned fbits_abs(float v) {
    return __float_as_uint(fabsf(v));
}
__device__ __forceinline__ float to_tf32(float v) {
    unsigned u;
    asm("cvt.rna.tf32.f32 %0, %1;" : "=r"(u) : "f"(v));
    return __uint_as_float(u);
}

// ---------------- exact radix select (value at ascending rank j) ----------------
__global__ void k_sel_init(unsigned j) {
    int t = threadIdx.x;
    if (t < 256) g_hist[t] = 0u;
    if (t == 0) { g_prefix = 0u; g_rank = j; g_nLess = 0u; g_nTie = 0u; }
}

__global__ void k_hist(const float* __restrict__ s, int n, int shift) {
    __shared__ unsigned h[256];
    h[threadIdx.x] = 0u;
    __syncthreads();
    unsigned prefix = g_prefix;
    int stride = gridDim.x * blockDim.x;
    for (int i = blockIdx.x * blockDim.x + threadIdx.x; i < n; i += stride) {
        unsigned bits = fbits_abs(s[i]);
        bool ok = (shift == 24) ? true : (((bits ^ prefix) >> (shift + 8)) == 0u);
        if (ok) atomicAdd(&h[(bits >> shift) & 0xFFu], 1u);
    }
    __syncthreads();
    if (h[threadIdx.x]) atomicAdd(&g_hist[threadIdx.x], h[threadIdx.x]);
}

__global__ void k_scan(int shift, int sel) {   // <<<1,1>>>
    unsigned r = g_rank;
    unsigned cum = 0u;
    int d = 0;
    for (d = 0; d < 256; d++) {
        unsigned c = g_hist[d];
        if (cum + c > r) break;
        cum += c;
    }
    if (d > 255) d = 255; // safety
    g_prefix = g_prefix | ((unsigned)d << shift);
    g_rank = r - cum;
    for (int i = 0; i < 256; i++) g_hist[i] = 0u;
    if (shift == 0) g_T[sel] = g_prefix;
}

__global__ void k_count_ties(const float* __restrict__ s, int n, int sel) {
    unsigned T = g_T[sel];
    int stride = gridDim.x * blockDim.x;
    for (int i = blockIdx.x * blockDim.x + threadIdx.x; i < n; i += stride) {
        unsigned bits = fbits_abs(s[i]);
        if (bits < T) atomicAdd(&g_nLess, 1u);
        else if (bits == T) {
            unsigned p = atomicAdd(&g_nTie, 1u);
            if (p < 8192u) g_tieIdx[p] = (unsigned)i;
        }
    }
}

// among ties (all == T), the r2 = j - nLess smallest indices get mask 0 (stable argsort).
// cutoff = (r2)-th smallest tie index; mask1 for tie iff idx >= cutoff.
__global__ void k_resolve(unsigned j, int sel) {   // <<<1,256>>>
    unsigned nLess = g_nLess;
    unsigned nTie = g_nTie; if (nTie > 8192u) nTie = 8192u;
    unsigned r2 = j - nLess;
    if (threadIdx.x == 0) {
        if (r2 >= nTie) g_cutoff[sel] = 0xFFFFFFFFu;   // (shouldn't happen; all ties 0)
    }
    if (r2 < nTie) {
        for (unsigned t = threadIdx.x; t < nTie; t += blockDim.x) {
            unsigned mi = g_tieIdx[t];
            unsigned cnt = 0;
            for (unsigned u = 0; u < nTie; u++) cnt += (g_tieIdx[u] < mi) ? 1u : 0u;
            if (cnt == r2) g_cutoff[sel] = mi;
        }
    }
}

// ---------------- build masked weights / convert x ----------------
__global__ void k_build_w1m(const float* __restrict__ w1, const float* __restrict__ s1) {
    int i = blockIdx.x * blockDim.x + threadIdx.x;
    if (i >= NK1) return;
    unsigned bits = fbits_abs(s1[i]);
    unsigned T = g_T[0], cut = g_cutoff[0];
    bool keep = (bits > T) || (bits == T && (unsigned)i >= cut);
    g_w1m[i] = keep ? to_tf32(w1[i]) : 0.0f;
}

__global__ void k_build_w2m(const float* __restrict__ w2, const float* __restrict__ s2) {
    int i = blockIdx.x * blockDim.x + threadIdx.x;
    if (i >= NK2) return;
    unsigned bits = fbits_abs(s2[i]);
    unsigned T = g_T[1], cut = g_cutoff[1];
    bool keep = (bits > T) || (bits == T && (unsigned)i >= cut);
    g_w2m[i] = keep ? w2[i] : 0.0f;
}

__global__ void k_cvt_x(const float* __restrict__ x) {
    int i = blockIdx.x * blockDim.x + threadIdx.x;
    if (i < MDIM * KDIM) g_xt[i] = to_tf32(x[i]);
}

// ---------------- fused GEMM1 (tf32 mma.sync) + partial second GEMM ----------------
__device__ __forceinline__ void mma_tf32(float* d, const unsigned* a, const unsigned* b) {
    asm volatile(
        "mma.sync.aligned.m16n8k8.row.col.f32.tf32.tf32.f32 "
        "{%0,%1,%2,%3}, {%4,%5,%6,%7}, {%8,%9}, {%0,%1,%2,%3};\n"
        : "+f"(d[0]), "+f"(d[1]), "+f"(d[2]), "+f"(d[3])
        : "r"(a[0]), "r"(a[1]), "r"(a[2]), "r"(a[3]), "r"(b[0]), "r"(b[1]));
}

__global__ void __launch_bounds__(256, 2) k_gemm1() {
    __shared__ float As[BM * LDT];
    __shared__ float Bs[BN * LDT];
    __shared__ float W2s[CDIM * BN];
    __shared__ float Part[BM * CDIM];

    const int tid = threadIdx.x;
    const int nt = blockIdx.x;   // 0..63
    const int mt = blockIdx.y;   // 0..127
    const float* Ag = g_xt  + (size_t)mt * BM * KDIM;
    const float* Bg = g_w1m + (size_t)nt * BN * KDIM;

    // load w2 slice + zero partial accumulator (covered by first sync in loop)
    for (int p = tid; p < CDIM * BN; p += 256)
        W2s[p] = g_w2m[(p >> 7) * NDIM + nt * BN + (p & 127)];
    for (int p = tid; p < BM * CDIM; p += 256)
        Part[p] = 0.0f;

    const int wid = tid >> 5, lane = tid & 31;
    const int mw = wid & 1, nw = wid >> 1;   // 2 x 4 warp grid -> warp tile 64 x 32
    const int g4 = lane >> 2, t4 = lane & 3;

    float d[4][4][4];
#pragma unroll
    for (int i = 0; i < 4; i++)
#pragma unroll
        for (int j = 0; j < 4; j++)
#pragma unroll
            for (int r = 0; r < 4; r++) d[i][j][r] = 0.0f;

    // software pipeline: prefetch gmem tile into regs while computing
    const int r0 = tid >> 2;                 // 0..63 rows (x2 with +256 offset)
    const int c4 = (tid & 3) << 2;           // 0,4,8,12
    float4 pa0, pa1, pb0, pb1;
    {
        int k0 = 0;
        pa0 = *(const float4*)(Ag + (size_t)r0 * KDIM + k0 + c4);
        pa1 = *(const float4*)(Ag + (size_t)(r0 + 64) * KDIM + k0 + c4);
        pb0 = *(const float4*)(Bg + (size_t)r0 * KDIM + k0 + c4);
        pb1 = *(const float4*)(Bg + (size_t)(r0 + 64) * KDIM + k0 + c4);
    }

    for (int kk = 0; kk < KDIM / BKT; kk++) {
        __syncthreads();  // smem free to overwrite
        *(float4*)(As + r0 * LDT + c4) = pa0;
        *(float4*)(As + (r0 + 64) * LDT + c4) = pa1;
        *(float4*)(Bs + r0 * LDT + c4) = pb0;
        *(float4*)(Bs + (r0 + 64) * LDT + c4) = pb1;
        __syncthreads();

        if (kk + 1 < KDIM / BKT) {
            int k0 = (kk + 1) * BKT;
            pa0 = *(const float4*)(Ag + (size_t)r0 * KDIM + k0 + c4);
            pa1 = *(const float4*)(Ag + (size_t)(r0 + 64) * KDIM + k0 + c4);
            pb0 = *(const float4*)(Bg + (size_t)r0 * KDIM + k0 + c4);
            pb1 = *(const float4*)(Bg + (size_t)(r0 + 64) * KDIM + k0 + c4);
        }

#pragma unroll
        for (int ks = 0; ks < 2; ks++) {
            const int kb = ks * 8;
            unsigned a[4][4], b[4][2];
#pragma unroll
            for (int i = 0; i < 4; i++) {
                int ra = mw * 64 + i * 16 + g4;
                a[i][0] = __float_as_uint(As[ra * LDT + kb + t4]);
                a[i][1] = __float_as_uint(As[(ra + 8) * LDT + kb + t4]);
                a[i][2] = __float_as_uint(As[ra * LDT + kb + t4 + 4]);
                a[i][3] = __float_as_uint(As[(ra + 8) * LDT + kb + t4 + 4]);
            }
#pragma unroll
            for (int j = 0; j < 4; j++) {
                int rb = nw * 32 + j * 8 + g4;
                b[j][0] = __float_as_uint(Bs[rb * LDT + kb + t4]);
                b[j][1] = __float_as_uint(Bs[rb * LDT + kb + t4 + 4]);
            }
#pragma unroll
            for (int i = 0; i < 4; i++)
#pragma unroll
                for (int j = 0; j < 4; j++)
                    mma_tf32(d[i][j], a[i], b[j]);
        }
    }
    __syncthreads();

    // epilogue: relu + contract with w2 slice into Part[row][c]
#pragma unroll
    for (int i = 0; i < 4; i++) {
#pragma unroll
        for (int h = 0; h < 2; h++) {
            const int row = mw * 64 + i * 16 + g4 + h * 8;
            float v[8];
#pragma unroll
            for (int j = 0; j < 4; j++) {
                v[2 * j + 0] = fmaxf(d[i][j][h * 2 + 0], 0.0f);
                v[2 * j + 1] = fmaxf(d[i][j][h * 2 + 1], 0.0f);
            }
#pragma unroll
            for (int c = 0; c < CDIM; c++) {
                float s = 0.0f;
#pragma unroll
                for (int j = 0; j < 4; j++) {
                    int col = nw * 32 + j * 8 + 2 * t4;
                    s += v[2 * j + 0] * W2s[c * BN + col];
                    s += v[2 * j + 1] * W2s[c * BN + col + 1];
                }
                s += __shfl_xor_sync(0xFFFFFFFFu, s, 1);
                s += __shfl_xor_sync(0xFFFFFFFFu, s, 2);
                if (t4 == 0) atomicAdd(&Part[row * CDIM + c], s);
            }
        }
    }
    __syncthreads();

    float* outp = g_part + (size_t)nt * (MDIM * CDIM) + (size_t)mt * (BM * CDIM);
    for (int p = tid; p < BM * CDIM; p += 256) outp[p] = Part[p];
}

// ---------------- reduce partials + log_softmax ----------------
__global__ void k_reduce(float* __restrict__ out) {   // <<<512, 320>>>
    const int tid = threadIdx.x;            // 0..319 : 32 rows x 10 classes
    const int base = blockIdx.x * 32 * CDIM;
    float s = 0.0f;
#pragma unroll 8
    for (int nt = 0; nt < NTILES; nt++)
        s += g_part[(size_t)nt * (MDIM * CDIM) + base + tid];
    __shared__ float L[32 * CDIM];
    L[tid] = s;
    __syncthreads();
    const int rl = tid / CDIM;
    float m = -INFINITY;
#pragma unroll
    for (int c = 0; c < CDIM; c++) m = fmaxf(m, L[rl * CDIM + c]);
    float se = 0.0f;
#pragma unroll
    for (int c = 0; c < CDIM; c++) se += expf(L[rl * CDIM + c] - m);
    out[base + tid] = s - m - logf(se);
}

// ---------------- launch ----------------
static void run_select(const float* scores, int n, unsigned j, int sel) {
    int blocks = 1184;
    k_sel_init<<<1, 256>>>(j);
    k_hist<<<blocks, 256>>>(scores, n, 24);
    k_scan<<<1, 1>>>(24, sel);
    k_hist<<<blocks, 256>>>(scores, n, 16);
    k_scan<<<1, 1>>>(16, sel);
    k_hist<<<blocks, 256>>>(scores, n, 8);
    k_scan<<<1, 1>>>(8, sel);
    k_hist<<<blocks, 256>>>(scores, n, 0);
    k_scan<<<1, 1>>>(0, sel);
    k_count_ties<<<blocks, 256>>>(scores, n, sel);
    k_resolve<<<1, 256>>>(j, sel);
}

extern "C" void kernel_launch(void* const* d_in, const int* in_sizes, int n_in,
                              void* d_out, int out_size) {
    const float* x  = (const float*)d_in[0];
    const float* w1 = (const float*)d_in[1];
    const float* s1 = (const float*)d_in[2];
    const float* w2 = (const float*)d_in[3];
    const float* s2 = (const float*)d_in[4];
    float* out = (float*)d_out;

    run_select(s1, NK1, J1, 0);
    run_select(s2, NK2, J2, 1);

    k_build_w1m<<<(NK1 + 255) / 256, 256>>>(w1, s1);
    k_build_w2m<<<(NK2 + 255) / 256, 256>>>(w2, s2);
    k_cvt_x<<<(MDIM * KDIM + 255) / 256, 256>>>(x);

    dim3 grid(NTILES, MDIM / BM);   // (64, 128)
    k_gemm1<<<grid, 256>>>();

    k_reduce<<<MDIM / 32, 32 * CDIM>>>(out);
}

// round 3
// speedup vs baseline: 1.2849x; 1.2849x over previous
#include <cuda_runtime.h>
#include <math.h>
#include <stdint.h>

// Problem dims
#define MDIM  16384
#define KDIM  784
#define KPAD  800                  // 25 chunks of 32 (zero padded)
#define NDIM  8192
#define CDIM  10
#define NK1   (NDIM * KDIM)        // 6,422,528
#define NK2   (CDIM * NDIM)        // 81,920
#define J1    3211264u             // int(0.5 * NK1)
#define J2    40960u               // int(0.5 * NK2)

// GEMM tiling (legacy mma.sync tf32, m16n8k8)
#define BM 128
#define BN 256
#define KCH 32                     // K per stage (128 bytes per row)
#define NITER (KPAD / KCH)         // 25
#define STAGES 4
#define NT2 (NDIM / BN)            // 32 N-tiles

// smem layout (dynamic)
#define OFF_A 0                                   // STAGES x 16384 (128 rows x 128B)
#define OFF_B (STAGES * 16384)                    // STAGES x 32768 (256 rows x 128B)
#define OFF_W2 (OFF_B + STAGES * 32768)           // 196608
#define OFF_PART (OFF_W2 + CDIM * BN * 4)         // 206848
#define SMEM_TOTAL (OFF_PART + BM * CDIM * 4)     // 211968

// ---------------- scratch (device globals; no allocation allowed) ----------------
__device__ float    g_xt[MDIM * KPAD];           // tf32-rounded x, K padded
__device__ float    g_w1m[NDIM * KPAD];          // masked+tf32 w1, K padded
__device__ float    g_w2m[CDIM * NDIM];          // masked w2 (fp32)
__device__ float    g_part[NT2 * MDIM * CDIM];   // partial logits per N-tile
__device__ unsigned g_hist[256];
__device__ unsigned g_prefix;
__device__ unsigned g_rank;
__device__ unsigned g_nLess;
__device__ unsigned g_nTie;
__device__ unsigned g_T[2];
__device__ unsigned g_cutoff[2];
__device__ unsigned g_tieIdx[8192];

__device__ __forceinline__ unsigned fbits_abs(float v) {
    return __float_as_uint(fabsf(v));
}
__device__ __forceinline__ float to_tf32(float v) {
    unsigned u;
    asm("cvt.rna.tf32.f32 %0, %1;" : "=r"(u) : "f"(v));
    return __uint_as_float(u);
}
__device__ __forceinline__ uint32_t smem_u32(const void* p) {
    uint32_t a;
    asm("{ .reg .u64 t; cvta.to.shared.u64 t, %1; cvt.u32.u64 %0, t; }" : "=r"(a) : "l"(p));
    return a;
}

// ---------------- low-level helpers ----------------
__device__ __forceinline__ void cp16(uint32_t dst, const void* src) {
    asm volatile("cp.async.cg.shared.global [%0], [%1], 16;" :: "r"(dst), "l"(src));
}
#define CP_COMMIT() asm volatile("cp.async.commit_group;" ::: "memory")
#define CP_WAIT(n)  asm volatile("cp.async.wait_group %0;" :: "n"(n) : "memory")

// ldmatrix x4 on tf32 data: each "row" address = 16B = 4 tf32 values.
__device__ __forceinline__ void ldsm4(unsigned& r0, unsigned& r1, unsigned& r2, unsigned& r3,
                                      uint32_t addr) {
    asm volatile("ldmatrix.sync.aligned.m8n8.x4.shared.b16 {%0,%1,%2,%3}, [%4];"
                 : "=r"(r0), "=r"(r1), "=r"(r2), "=r"(r3) : "r"(addr));
}

__device__ __forceinline__ void mma_tf32(float* d, const unsigned* a, const unsigned* b) {
    asm volatile(
        "mma.sync.aligned.m16n8k8.row.col.f32.tf32.tf32.f32 "
        "{%0,%1,%2,%3}, {%4,%5,%6,%7}, {%8,%9}, {%0,%1,%2,%3};\n"
        : "+f"(d[0]), "+f"(d[1]), "+f"(d[2]), "+f"(d[3])
        : "r"(a[0]), "r"(a[1]), "r"(a[2]), "r"(a[3]), "r"(b[0]), "r"(b[1]));
}

// SW128-style swizzle over 128B rows: 16B-unit index u XORed with (row & 7)
__device__ __forceinline__ uint32_t sw_off(uint32_t row, uint32_t u) {
    return row * 128u + ((u ^ (row & 7u)) << 4);
}

// ---------------- exact radix select (value at ascending rank j) ----------------
__global__ void k_sel_init(unsigned j) {
    int t = threadIdx.x;
    if (t < 256) g_hist[t] = 0u;
    if (t == 0) { g_prefix = 0u; g_rank = j; g_nLess = 0u; g_nTie = 0u; }
}

__global__ void k_hist(const float* __restrict__ s, int n, int shift) {
    __shared__ unsigned h[256];
    h[threadIdx.x] = 0u;
    __syncthreads();
    unsigned prefix = g_prefix;
    int stride = gridDim.x * blockDim.x;
    for (int i = blockIdx.x * blockDim.x + threadIdx.x; i < n; i += stride) {
        unsigned bits = fbits_abs(s[i]);
        bool ok = (shift == 24) ? true : (((bits ^ prefix) >> (shift + 8)) == 0u);
        if (ok) atomicAdd(&h[(bits >> shift) & 0xFFu], 1u);
    }
    __syncthreads();
    if (h[threadIdx.x]) atomicAdd(&g_hist[threadIdx.x], h[threadIdx.x]);
}

__global__ void k_scan(int shift, int sel) {   // <<<1,1>>>
    unsigned r = g_rank;
    unsigned cum = 0u;
    int d = 0;
    for (d = 0; d < 256; d++) {
        unsigned c = g_hist[d];
        if (cum + c > r) break;
        cum += c;
    }
    if (d > 255) d = 255;
    g_prefix = g_prefix | ((unsigned)d << shift);
    g_rank = r - cum;
    for (int i = 0; i < 256; i++) g_hist[i] = 0u;
    if (shift == 0) g_T[sel] = g_prefix;
}

__global__ void k_count_ties(const float* __restrict__ s, int n, int sel) {
    unsigned T = g_T[sel];
    int stride = gridDim.x * blockDim.x;
    for (int i = blockIdx.x * blockDim.x + threadIdx.x; i < n; i += stride) {
        unsigned bits = fbits_abs(s[i]);
        if (bits < T) atomicAdd(&g_nLess, 1u);
        else if (bits == T) {
            unsigned p = atomicAdd(&g_nTie, 1u);
            if (p < 8192u) g_tieIdx[p] = (unsigned)i;
        }
    }
}

__global__ void k_resolve(unsigned j, int sel) {   // <<<1,256>>>
    unsigned nLess = g_nLess;
    unsigned nTie = g_nTie; if (nTie > 8192u) nTie = 8192u;
    unsigned r2 = j - nLess;
    if (threadIdx.x == 0) {
        if (r2 >= nTie) g_cutoff[sel] = 0xFFFFFFFFu;
    }
    if (r2 < nTie) {
        for (unsigned t = threadIdx.x; t < nTie; t += blockDim.x) {
            unsigned mi = g_tieIdx[t];
            unsigned cnt = 0;
            for (unsigned u = 0; u < nTie; u++) cnt += (g_tieIdx[u] < mi) ? 1u : 0u;
            if (cnt == r2) g_cutoff[sel] = mi;
        }
    }
}

// ---------------- build masked weights / convert x (KPAD layout) ----------------
__global__ void k_build_w1m(const float* __restrict__ w1, const float* __restrict__ s1) {
    int i = blockIdx.x * blockDim.x + threadIdx.x;
    if (i >= NDIM * KPAD) return;
    int row = i / KPAD, k = i % KPAD;
    float v = 0.0f;
    if (k < KDIM) {
        int src = row * KDIM + k;
        unsigned bits = fbits_abs(s1[src]);
        unsigned T = g_T[0], cut = g_cutoff[0];
        bool keep = (bits > T) || (bits == T && (unsigned)src >= cut);
        v = keep ? to_tf32(w1[src]) : 0.0f;
    }
    g_w1m[i] = v;
}

__global__ void k_build_w2m(const float* __restrict__ w2, const float* __restrict__ s2) {
    int i = blockIdx.x * blockDim.x + threadIdx.x;
    if (i >= NK2) return;
    unsigned bits = fbits_abs(s2[i]);
    unsigned T = g_T[1], cut = g_cutoff[1];
    bool keep = (bits > T) || (bits == T && (unsigned)i >= cut);
    g_w2m[i] = keep ? w2[i] : 0.0f;
}

__global__ void k_cvt_x(const float* __restrict__ x) {
    int i = blockIdx.x * blockDim.x + threadIdx.x;   // MDIM * 200 float4 units
    if (i >= MDIM * (KPAD / 4)) return;
    int row = i / (KPAD / 4), c4 = (i % (KPAD / 4)) * 4;
    float4 v = make_float4(0.f, 0.f, 0.f, 0.f);
    if (c4 < KDIM) {
        v = *(const float4*)(x + (size_t)row * KDIM + c4);
        v.x = to_tf32(v.x); v.y = to_tf32(v.y); v.z = to_tf32(v.z); v.w = to_tf32(v.w);
    }
    *(float4*)(g_xt + (size_t)row * KPAD + c4) = v;
}

// ---------------- GEMM1 (tf32 mma.sync, 64x64 warp tiles) + fused relu/w2 epilogue ----------------
__global__ void __launch_bounds__(256, 1) k_gemm1() {
    extern __shared__ __align__(1024) char smem[];
    const uint32_t sb = smem_u32(smem);
    const int tid = threadIdx.x;
    const int nt = blockIdx.x;   // 0..31 (N tiles of 256)
    const int mt = blockIdx.y;   // 0..127 (M tiles of 128)

    const int wid = tid >> 5, lane = tid & 31;
    const int mw = wid & 1;      // 2 M warp-blocks of 64
    const int nw = wid >> 1;     // 4 N warp-blocks of 64
    const int g4 = lane >> 2, t4 = lane & 3;
    const int r8 = lane & 7;

    // w2 slice -> smem  [c][col 0..255]; Part zeroed
    float* W2s  = (float*)(smem + OFF_W2);
    float* Part = (float*)(smem + OFF_PART);
    for (int p = tid; p < CDIM * BN; p += 256)
        W2s[p] = g_w2m[(p >> 8) * NDIM + nt * BN + (p & 255)];
    for (int p = tid; p < BM * CDIM; p += 256)
        Part[p] = 0.0f;

    const char* Ag = (const char*)(g_xt  + (size_t)(mt * BM) * KPAD);
    const char* Bg = (const char*)(g_w1m + (size_t)(nt * BN) * KPAD);

    // cp.async writer mapping (per thread): contiguous 16B units
    // A: 1024 units, B: 2048 units
    // ldmatrix per-thread addressing
    const uint32_t aRowL = (uint32_t)(mw * 64 + ((lane >> 3) & 1) * 8 + r8);
    const uint32_t uA    = (uint32_t)(lane >> 4);          // 0/1: k-lo/k-hi half
    const uint32_t bRowL = (uint32_t)(nw * 64 + (lane >> 4) * 8 + r8);
    const uint32_t uB    = (uint32_t)((lane >> 3) & 1);

    float d[4][8][4];
#pragma unroll
    for (int i = 0; i < 4; i++)
#pragma unroll
        for (int j = 0; j < 8; j++)
#pragma unroll
            for (int r = 0; r < 4; r++) d[i][j][r] = 0.0f;

    // ---- issue helper (stage st into slot st&3) via lambda-free macro style ----
#define ISSUE_STAGE(st) do {                                                      \
    const int _s = (st) & (STAGES - 1);                                           \
    const char* _ab = Ag + (size_t)(st) * (KCH * 4);                              \
    const char* _bb = Bg + (size_t)(st) * (KCH * 4);                              \
    _Pragma("unroll")                                                             \
    for (int q = 0; q < 4; q++) {                                                 \
        int idx = tid + q * 256;                                                  \
        uint32_t row = (uint32_t)(idx >> 3), u = (uint32_t)(idx & 7);             \
        cp16(sb + OFF_A + _s * 16384 + sw_off(row, u),                            \
             _ab + (size_t)row * (KPAD * 4) + u * 16);                            \
    }                                                                             \
    _Pragma("unroll")                                                             \
    for (int q = 0; q < 8; q++) {                                                 \
        int idx = tid + q * 256;                                                  \
        uint32_t row = (uint32_t)(idx >> 3), u = (uint32_t)(idx & 7);             \
        cp16(sb + OFF_B + _s * 32768 + sw_off(row, u),                            \
             _bb + (size_t)row * (KPAD * 4) + u * 16);                            \
    }                                                                             \
} while (0)

    // prologue: 3 stages in flight
    ISSUE_STAGE(0); CP_COMMIT();
    ISSUE_STAGE(1); CP_COMMIT();
    ISSUE_STAGE(2); CP_COMMIT();

    for (int kk = 0; kk < NITER; kk++) {
        CP_WAIT(2);
        __syncthreads();
        const uint32_t aB = sb + OFF_A + (kk & 3) * 16384;
        const uint32_t bB = sb + OFF_B + (kk & 3) * 32768;
#pragma unroll
        for (int q8 = 0; q8 < 4; q8++) {       // four K=8 slices per stage
            const uint32_t ul = (uint32_t)(2 * q8);
            unsigned A4[4][4], B4[4][4];
#pragma unroll
            for (int i = 0; i < 4; i++) {
                uint32_t row = aRowL + (uint32_t)(i * 16);
                ldsm4(A4[i][0], A4[i][1], A4[i][2], A4[i][3],
                      aB + sw_off(row, ul + uA));
            }
#pragma unroll
            for (int j2 = 0; j2 < 4; j2++) {
                uint32_t row = bRowL + (uint32_t)(j2 * 16);
                ldsm4(B4[j2][0], B4[j2][1], B4[j2][2], B4[j2][3],
                      bB + sw_off(row, ul + uB));
            }
#pragma unroll
            for (int i = 0; i < 4; i++)
#pragma unroll
                for (int j = 0; j < 8; j++)
                    mma_tf32(d[i][j], A4[i], &B4[j >> 1][2 * (j & 1)]);
        }
        __syncthreads();
        const int nx = kk + 3;
        if (nx < NITER) ISSUE_STAGE(nx);
        CP_COMMIT();
    }

    // ---- epilogue: relu + contract with w2 slice ----
#pragma unroll
    for (int i = 0; i < 4; i++) {
#pragma unroll
        for (int h = 0; h < 2; h++) {
            const int row = mw * 64 + i * 16 + g4 + h * 8;
            float v0[8], v1[8];
#pragma unroll
            for (int j = 0; j < 8; j++) {
                v0[j] = fmaxf(d[i][j][2 * h + 0], 0.0f);
                v1[j] = fmaxf(d[i][j][2 * h + 1], 0.0f);
            }
#pragma unroll
            for (int c = 0; c < CDIM; c++) {
                float s = 0.0f;
#pragma unroll
                for (int j = 0; j < 8; j++) {
                    float2 w = *(const float2*)&W2s[c * BN + nw * 64 + j * 8 + 2 * t4];
                    s += v0[j] * w.x + v1[j] * w.y;
                }
                s += __shfl_xor_sync(0xFFFFFFFFu, s, 1);
                s += __shfl_xor_sync(0xFFFFFFFFu, s, 2);
                if (t4 == 0) atomicAdd(&Part[row * CDIM + c], s);
            }
        }
    }
    __syncthreads();

    float* outp = g_part + (size_t)nt * (MDIM * CDIM) + (size_t)(mt * BM) * CDIM;
    for (int p = tid; p < BM * CDIM; p += 256) outp[p] = Part[p];
#undef ISSUE_STAGE
}

// ---------------- reduce partials + log_softmax ----------------
__global__ void k_reduce(float* __restrict__ out) {   // <<<512, 320>>>
    const int tid = threadIdx.x;            // 32 rows x 10 classes
    const int base = blockIdx.x * 32 * CDIM;
    float s = 0.0f;
#pragma unroll 8
    for (int nt = 0; nt < NT2; nt++)
        s += g_part[(size_t)nt * (MDIM * CDIM) + base + tid];
    __shared__ float L[32 * CDIM];
    L[tid] = s;
    __syncthreads();
    const int rl = tid / CDIM;
    float m = -INFINITY;
#pragma unroll
    for (int c = 0; c < CDIM; c++) m = fmaxf(m, L[rl * CDIM + c]);
    float se = 0.0f;
#pragma unroll
    for (int c = 0; c < CDIM; c++) se += expf(L[rl * CDIM + c] - m);
    out[base + tid] = s - m - logf(se);
}

// ---------------- launch ----------------
static void run_select(const float* scores, int n, unsigned j, int sel) {
    int blocks = 1184;
    k_sel_init<<<1, 256>>>(j);
    k_hist<<<blocks, 256>>>(scores, n, 24);
    k_scan<<<1, 1>>>(24, sel);
    k_hist<<<blocks, 256>>>(scores, n, 16);
    k_scan<<<1, 1>>>(16, sel);
    k_hist<<<blocks, 256>>>(scores, n, 8);
    k_scan<<<1, 1>>>(8, sel);
    k_hist<<<blocks, 256>>>(scores, n, 0);
    k_scan<<<1, 1>>>(0, sel);
    k_count_ties<<<blocks, 256>>>(scores, n, sel);
    k_resolve<<<1, 256>>>(j, sel);
}

extern "C" void kernel_launch(void* const* d_in, const int* in_sizes, int n_in,
                              void* d_out, int out_size) {
    const float* x  = (const float*)d_in[0];
    const float* w1 = (const float*)d_in[1];
    const float* s1 = (const float*)d_in[2];
    const float* w2 = (const float*)d_in[3];
    const float* s2 = (const float*)d_in[4];
    float* out = (float*)d_out;

    cudaFuncSetAttribute(k_gemm1, cudaFuncAttributeMaxDynamicSharedMemorySize, SMEM_TOTAL);

    run_select(s1, NK1, J1, 0);
    run_select(s2, NK2, J2, 1);

    k_build_w1m<<<(NDIM * KPAD + 255) / 256, 256>>>(w1, s1);
    k_build_w2m<<<(NK2 + 255) / 256, 256>>>(w2, s2);
    k_cvt_x<<<(MDIM * (KPAD / 4) + 255) / 256, 256>>>(x);

    dim3 grid(NT2, MDIM / BM);   // (32, 128)
    k_gemm1<<<grid, 256, SMEM_TOTAL>>>();

    k_reduce<<<MDIM / 32, 32 * CDIM>>>(out);
}

// round 4
// speedup vs baseline: 1.8688x; 1.4545x over previous
#include <cuda_runtime.h>
#include <cuda_fp16.h>
#include <math.h>
#include <stdint.h>

// Problem dims
#define MDIM  16384
#define KDIM  784
#define KPAD  832                  // 13 chunks of 64 (zero padded)
#define NDIM  8192
#define CDIM  10
#define NK1   (NDIM * KDIM)        // 6,422,528
#define NK2   (CDIM * NDIM)        // 81,920
#define J1    3211264u             // int(0.5 * NK1)
#define J2    40960u               // int(0.5 * NK2)

// GEMM tiling (legacy mma.sync fp16, m16n8k16)
#define BM 128
#define BN 256
#define KCH 64                     // K per stage (64 fp16 = 128 bytes per row)
#define NITER (KPAD / KCH)         // 13
#define STAGES 4
#define NT2 (NDIM / BN)            // 32 N-tiles

// smem layout (dynamic)
#define OFF_A 0                                   // STAGES x 16384 (128 rows x 128B)
#define OFF_B (STAGES * 16384)                    // STAGES x 32768 (256 rows x 128B)
#define OFF_W2 (OFF_B + STAGES * 32768)           // 196608
#define OFF_PART (OFF_W2 + CDIM * BN * 4)         // 206848
#define SMEM_TOTAL (OFF_PART + BM * CDIM * 4)     // 211968

// ---------------- scratch (device globals; no allocation allowed) ----------------
__device__ __half   g_xh[MDIM * KPAD];           // fp16 x, K padded
__device__ __half   g_w1h[NDIM * KPAD];          // masked fp16 w1, K padded
__device__ float    g_w2m[CDIM * NDIM];          // masked w2 (fp32)
__device__ float    g_part[NT2 * MDIM * CDIM];   // partial logits per N-tile
__device__ unsigned g_hist[256];
__device__ unsigned g_prefix;
__device__ unsigned g_rank;
__device__ unsigned g_nLess;
__device__ unsigned g_nTie;
__device__ unsigned g_T[2];
__device__ unsigned g_cutoff[2];
__device__ unsigned g_tieIdx[8192];

__device__ __forceinline__ unsigned fbits_abs(float v) {
    return __float_as_uint(fabsf(v));
}
__device__ __forceinline__ uint32_t smem_u32(const void* p) {
    uint32_t a;
    asm("{ .reg .u64 t; cvta.to.shared.u64 t, %1; cvt.u32.u64 %0, t; }" : "=r"(a) : "l"(p));
    return a;
}

// ---------------- low-level helpers ----------------
__device__ __forceinline__ void cp16(uint32_t dst, const void* src) {
    asm volatile("cp.async.cg.shared.global [%0], [%1], 16;" :: "r"(dst), "l"(src));
}
#define CP_COMMIT() asm volatile("cp.async.commit_group;" ::: "memory")
#define CP_WAIT(n)  asm volatile("cp.async.wait_group %0;" :: "n"(n) : "memory")

__device__ __forceinline__ void ldsm4(unsigned& r0, unsigned& r1, unsigned& r2, unsigned& r3,
                                      uint32_t addr) {
    asm volatile("ldmatrix.sync.aligned.m8n8.x4.shared.b16 {%0,%1,%2,%3}, [%4];"
                 : "=r"(r0), "=r"(r1), "=r"(r2), "=r"(r3) : "r"(addr));
}

__device__ __forceinline__ void mma_fp16(float* d, const unsigned* a, const unsigned* b) {
    asm volatile(
        "mma.sync.aligned.m16n8k16.row.col.f32.f16.f16.f32 "
        "{%0,%1,%2,%3}, {%4,%5,%6,%7}, {%8,%9}, {%0,%1,%2,%3};\n"
        : "+f"(d[0]), "+f"(d[1]), "+f"(d[2]), "+f"(d[3])
        : "r"(a[0]), "r"(a[1]), "r"(a[2]), "r"(a[3]), "r"(b[0]), "r"(b[1]));
}

// swizzle over 128B rows: 16B-unit index u XORed with (row & 7)
__device__ __forceinline__ uint32_t sw_off(uint32_t row, uint32_t u) {
    return row * 128u + ((u ^ (row & 7u)) << 4);
}

// ---------------- exact radix select (value at ascending rank j) ----------------
__global__ void k_sel_init(unsigned j) {
    int t = threadIdx.x;
    if (t < 256) g_hist[t] = 0u;
    if (t == 0) { g_prefix = 0u; g_rank = j; g_nLess = 0u; g_nTie = 0u; }
}

__global__ void k_hist(const float* __restrict__ s, int n, int shift) {
    __shared__ unsigned h[256];
    h[threadIdx.x] = 0u;
    __syncthreads();
    unsigned prefix = g_prefix;
    int n4 = n >> 2;
    int stride = gridDim.x * blockDim.x;
    const float4* s4 = (const float4*)s;
    for (int i = blockIdx.x * blockDim.x + threadIdx.x; i < n4; i += stride) {
        float4 v = s4[i];
        unsigned b0 = fbits_abs(v.x), b1 = fbits_abs(v.y);
        unsigned b2 = fbits_abs(v.z), b3 = fbits_abs(v.w);
        if (shift == 24) {
            atomicAdd(&h[b0 >> 24], 1u); atomicAdd(&h[b1 >> 24], 1u);
            atomicAdd(&h[b2 >> 24], 1u); atomicAdd(&h[b3 >> 24], 1u);
        } else {
            if (((b0 ^ prefix) >> (shift + 8)) == 0u) atomicAdd(&h[(b0 >> shift) & 0xFFu], 1u);
            if (((b1 ^ prefix) >> (shift + 8)) == 0u) atomicAdd(&h[(b1 >> shift) & 0xFFu], 1u);
            if (((b2 ^ prefix) >> (shift + 8)) == 0u) atomicAdd(&h[(b2 >> shift) & 0xFFu], 1u);
            if (((b3 ^ prefix) >> (shift + 8)) == 0u) atomicAdd(&h[(b3 >> shift) & 0xFFu], 1u);
        }
    }
    __syncthreads();
    if (h[threadIdx.x]) atomicAdd(&g_hist[threadIdx.x], h[threadIdx.x]);
}

__global__ void k_scan(int shift, int sel) {   // <<<1,1>>>
    unsigned r = g_rank;
    unsigned cum = 0u;
    int d = 0;
    for (d = 0; d < 256; d++) {
        unsigned c = g_hist[d];
        if (cum + c > r) break;
        cum += c;
    }
    if (d > 255) d = 255;
    g_prefix = g_prefix | ((unsigned)d << shift);
    g_rank = r - cum;
    for (int i = 0; i < 256; i++) g_hist[i] = 0u;
    if (shift == 0) g_T[sel] = g_prefix;
}

__global__ void k_count_ties(const float* __restrict__ s, int n, int sel) {
    unsigned T = g_T[sel];
    int stride = gridDim.x * blockDim.x;
    for (int i = blockIdx.x * blockDim.x + threadIdx.x; i < n; i += stride) {
        unsigned bits = fbits_abs(s[i]);
        if (bits < T) atomicAdd(&g_nLess, 1u);
        else if (bits == T) {
            unsigned p = atomicAdd(&g_nTie, 1u);
            if (p < 8192u) g_tieIdx[p] = (unsigned)i;
        }
    }
}

__global__ void k_resolve(unsigned j, int sel) {   // <<<1,256>>>
    unsigned nLess = g_nLess;
    unsigned nTie = g_nTie; if (nTie > 8192u) nTie = 8192u;
    unsigned r2 = j - nLess;
    if (threadIdx.x == 0) {
        if (r2 >= nTie) g_cutoff[sel] = 0xFFFFFFFFu;
    }
    if (r2 < nTie) {
        for (unsigned t = threadIdx.x; t < nTie; t += blockDim.x) {
            unsigned mi = g_tieIdx[t];
            unsigned cnt = 0;
            for (unsigned u = 0; u < nTie; u++) cnt += (g_tieIdx[u] < mi) ? 1u : 0u;
            if (cnt == r2) g_cutoff[sel] = mi;
        }
    }
}

// ---------------- build masked fp16 weights / convert x to fp16 ----------------
__global__ void k_build_w1h(const float* __restrict__ w1, const float* __restrict__ s1) {
    int i = blockIdx.x * blockDim.x + threadIdx.x;
    if (i >= NDIM * KPAD) return;
    int row = i / KPAD, k = i % KPAD;
    __half v = __float2half(0.0f);
    if (k < KDIM) {
        int src = row * KDIM + k;
        unsigned bits = fbits_abs(s1[src]);
        unsigned T = g_T[0], cut = g_cutoff[0];
        bool keep = (bits > T) || (bits == T && (unsigned)src >= cut);
        v = keep ? __float2half(w1[src]) : __float2half(0.0f);
    }
    g_w1h[i] = v;
}

__global__ void k_build_w2m(const float* __restrict__ w2, const float* __restrict__ s2) {
    int i = blockIdx.x * blockDim.x + threadIdx.x;
    if (i >= NK2) return;
    unsigned bits = fbits_abs(s2[i]);
    unsigned T = g_T[1], cut = g_cutoff[1];
    bool keep = (bits > T) || (bits == T && (unsigned)i >= cut);
    g_w2m[i] = keep ? w2[i] : 0.0f;
}

__global__ void k_cvt_xh(const float* __restrict__ x) {
    // one thread per 8 halves (16B store). 784 = 98*8, KPAD = 104*8.
    int i = blockIdx.x * blockDim.x + threadIdx.x;
    if (i >= MDIM * (KPAD / 8)) return;
    int row = i / (KPAD / 8), u = i % (KPAD / 8);
    int c8 = u * 8;
    __half2 h[4];
    if (c8 < KDIM) {
        const float4* p = (const float4*)(x + (size_t)row * KDIM + c8);
        float4 v0 = p[0], v1 = p[1];
        h[0] = __floats2half2_rn(v0.x, v0.y);
        h[1] = __floats2half2_rn(v0.z, v0.w);
        h[2] = __floats2half2_rn(v1.x, v1.y);
        h[3] = __floats2half2_rn(v1.z, v1.w);
    } else {
        h[0] = h[1] = h[2] = h[3] = __floats2half2_rn(0.0f, 0.0f);
    }
    *(uint4*)(g_xh + (size_t)row * KPAD + c8) = *(const uint4*)h;
}

// ---------------- GEMM1 (fp16 mma.sync, 64x64 warp tiles) + fused relu/w2 epilogue ----------------
__global__ void __launch_bounds__(256, 1) k_gemm1() {
    extern __shared__ __align__(1024) char smem[];
    const uint32_t sb = smem_u32(smem);
    const int tid = threadIdx.x;
    const int nt = blockIdx.x;   // 0..31 (N tiles of 256)
    const int mt = blockIdx.y;   // 0..127 (M tiles of 128)

    const int wid = tid >> 5, lane = tid & 31;
    const int mw = wid & 1;      // 2 M warp-blocks of 64
    const int nw = wid >> 1;     // 4 N warp-blocks of 64
    const int g4 = lane >> 2, t4 = lane & 3;
    const int r8 = lane & 7;

    float* W2s  = (float*)(smem + OFF_W2);
    float* Part = (float*)(smem + OFF_PART);
    for (int p = tid; p < CDIM * BN; p += 256)
        W2s[p] = g_w2m[(p >> 8) * NDIM + nt * BN + (p & 255)];
    for (int p = tid; p < BM * CDIM; p += 256)
        Part[p] = 0.0f;

    const char* Ag = (const char*)(g_xh  + (size_t)(mt * BM) * KPAD);
    const char* Bg = (const char*)(g_w1h + (size_t)(nt * BN) * KPAD);
    const size_t rowBytes = KPAD * 2;   // 1664

    // ldmatrix per-thread addressing
    // A frags: {m-lo k-lo, m-hi k-lo, m-lo k-hi, m-hi k-hi} = a0..a3 of m16n8k16
    const uint32_t aRowL = (uint32_t)(mw * 64 + ((lane >> 3) & 1) * 8 + r8);
    const uint32_t uA    = (uint32_t)(lane >> 4);          // k8-half within k16
    // B frags: {n-lo k-lo, n-lo k-hi, n-hi k-lo, n-hi k-hi}
    const uint32_t bRowL = (uint32_t)(nw * 64 + (lane >> 4) * 8 + r8);
    const uint32_t uB    = (uint32_t)((lane >> 3) & 1);

    float d[4][8][4];
#pragma unroll
    for (int i = 0; i < 4; i++)
#pragma unroll
        for (int j = 0; j < 8; j++)
#pragma unroll
            for (int r = 0; r < 4; r++) d[i][j][r] = 0.0f;

#define ISSUE_STAGE(st) do {                                                      \
    const int _s = (st) & (STAGES - 1);                                           \
    const char* _ab = Ag + (size_t)(st) * 128;                                    \
    const char* _bb = Bg + (size_t)(st) * 128;                                    \
    _Pragma("unroll")                                                             \
    for (int q = 0; q < 4; q++) {                                                 \
        int idx = tid + q * 256;                                                  \
        uint32_t row = (uint32_t)(idx >> 3), u = (uint32_t)(idx & 7);             \
        cp16(sb + OFF_A + _s * 16384 + sw_off(row, u),                            \
             _ab + (size_t)row * rowBytes + u * 16);                              \
    }                                                                             \
    _Pragma("unroll")                                                             \
    for (int q = 0; q < 8; q++) {                                                 \
        int idx = tid + q * 256;                                                  \
        uint32_t row = (uint32_t)(idx >> 3), u = (uint32_t)(idx & 7);             \
        cp16(sb + OFF_B + _s * 32768 + sw_off(row, u),                            \
             _bb + (size_t)row * rowBytes + u * 16);                              \
    }                                                                             \
} while (0)

    ISSUE_STAGE(0); CP_COMMIT();
    ISSUE_STAGE(1); CP_COMMIT();
    ISSUE_STAGE(2); CP_COMMIT();

    for (int kk = 0; kk < NITER; kk++) {
        CP_WAIT(2);
        __syncthreads();
        const uint32_t aB = sb + OFF_A + (kk & 3) * 16384;
        const uint32_t bB = sb + OFF_B + (kk & 3) * 32768;
#pragma unroll
        for (int ks = 0; ks < 4; ks++) {       // four K=16 slices per stage
            const uint32_t ul = (uint32_t)(2 * ks);
            unsigned A4[4][4], B4[4][4];
#pragma unroll
            for (int i = 0; i < 4; i++) {
                uint32_t row = aRowL + (uint32_t)(i * 16);
                ldsm4(A4[i][0], A4[i][1], A4[i][2], A4[i][3],
                      aB + sw_off(row, ul + uA));
            }
#pragma unroll
            for (int j2 = 0; j2 < 4; j2++) {
                uint32_t row = bRowL + (uint32_t)(j2 * 16);
                ldsm4(B4[j2][0], B4[j2][1], B4[j2][2], B4[j2][3],
                      bB + sw_off(row, ul + uB));
            }
#pragma unroll
            for (int i = 0; i < 4; i++)
#pragma unroll
                for (int j = 0; j < 8; j++)
                    mma_fp16(d[i][j], A4[i], &B4[j >> 1][2 * (j & 1)]);
        }
        // write slot (kk+3)&3 == (kk-1)&3: all its readers passed this iter's barrier
        const int nx = kk + 3;
        if (nx < NITER) ISSUE_STAGE(nx);
        CP_COMMIT();
    }

    // ---- epilogue: relu + contract with w2 slice ----
#pragma unroll
    for (int i = 0; i < 4; i++) {
#pragma unroll
        for (int h = 0; h < 2; h++) {
            const int row = mw * 64 + i * 16 + g4 + h * 8;
            float v0[8], v1[8];
#pragma unroll
            for (int j = 0; j < 8; j++) {
                v0[j] = fmaxf(d[i][j][2 * h + 0], 0.0f);
                v1[j] = fmaxf(d[i][j][2 * h + 1], 0.0f);
            }
#pragma unroll
            for (int c = 0; c < CDIM; c++) {
                float s = 0.0f;
#pragma unroll
                for (int j = 0; j < 8; j++) {
                    float2 w = *(const float2*)&W2s[c * BN + nw * 64 + j * 8 + 2 * t4];
                    s += v0[j] * w.x + v1[j] * w.y;
                }
                s += __shfl_xor_sync(0xFFFFFFFFu, s, 1);
                s += __shfl_xor_sync(0xFFFFFFFFu, s, 2);
                if (t4 == 0) atomicAdd(&Part[row * CDIM + c], s);
            }
        }
    }
    __syncthreads();

    float* outp = g_part + (size_t)nt * (MDIM * CDIM) + (size_t)(mt * BM) * CDIM;
    for (int p = tid; p < BM * CDIM; p += 256) outp[p] = Part[p];
#undef ISSUE_STAGE
}

// ---------------- reduce partials + log_softmax ----------------
__global__ void k_reduce(float* __restrict__ out) {   // <<<512, 320>>>
    const int tid = threadIdx.x;            // 32 rows x 10 classes
    const int base = blockIdx.x * 32 * CDIM;
    float s = 0.0f;
#pragma unroll 8
    for (int nt = 0; nt < NT2; nt++)
        s += g_part[(size_t)nt * (MDIM * CDIM) + base + tid];
    __shared__ float L[32 * CDIM];
    L[tid] = s;
    __syncthreads();
    const int rl = tid / CDIM;
    float m = -INFINITY;
#pragma unroll
    for (int c = 0; c < CDIM; c++) m = fmaxf(m, L[rl * CDIM + c]);
    float se = 0.0f;
#pragma unroll
    for (int c = 0; c < CDIM; c++) se += expf(L[rl * CDIM + c] - m);
    out[base + tid] = s - m - logf(se);
}

// ---------------- launch ----------------
static void run_select(const float* scores, int n, unsigned j, int sel) {
    int blocks = 1184;
    k_sel_init<<<1, 256>>>(j);
    k_hist<<<blocks, 256>>>(scores, n, 24);
    k_scan<<<1, 1>>>(24, sel);
    k_hist<<<blocks, 256>>>(scores, n, 16);
    k_scan<<<1, 1>>>(16, sel);
    k_hist<<<blocks, 256>>>(scores, n, 8);
    k_scan<<<1, 1>>>(8, sel);
    k_hist<<<blocks, 256>>>(scores, n, 0);
    k_scan<<<1, 1>>>(0, sel);
    k_count_ties<<<blocks, 256>>>(scores, n, sel);
    k_resolve<<<1, 256>>>(j, sel);
}

extern "C" void kernel_launch(void* const* d_in, const int* in_sizes, int n_in,
                              void* d_out, int out_size) {
    const float* x  = (const float*)d_in[0];
    const float* w1 = (const float*)d_in[1];
    const float* s1 = (const float*)d_in[2];
    const float* w2 = (const float*)d_in[3];
    const float* s2 = (const float*)d_in[4];
    float* out = (float*)d_out;

    cudaFuncSetAttribute(k_gemm1, cudaFuncAttributeMaxDynamicSharedMemorySize, SMEM_TOTAL);

    run_select(s1, NK1, J1, 0);
    run_select(s2, NK2, J2, 1);

    k_build_w1h<<<(NDIM * KPAD + 255) / 256, 256>>>(w1, s1);
    k_build_w2m<<<(NK2 + 255) / 256, 256>>>(w2, s2);
    k_cvt_xh<<<(MDIM * (KPAD / 8) + 255) / 256, 256>>>(x);

    dim3 grid(NT2, MDIM / BM);   // (32, 128)
    k_gemm1<<<grid, 256, SMEM_TOTAL>>>();

    k_reduce<<<MDIM / 32, 32 * CDIM>>>(out);
}

// round 5
// speedup vs baseline: 2.1602x; 1.1559x over previous
#include <cuda_runtime.h>
#include <cuda_fp16.h>
#include <math.h>
#include <stdint.h>

// Problem dims
#define MDIM  16384
#define KDIM  784
#define KPAD  832                  // 13 chunks of 64 (zero padded)
#define NDIM  8192
#define CDIM  10
#define NK1   (NDIM * KDIM)        // 6,422,528
#define NK2   (CDIM * NDIM)        // 81,920
#define J1    3211264u             // int(0.5 * NK1)
#define J2    40960u               // int(0.5 * NK2)

// GEMM tiling (legacy mma.sync fp16, m16n8k16)
#define BM 128
#define BN 256
#define KCH 64
#define NITER (KPAD / KCH)         // 13
#define STAGES 4
#define NT2 (NDIM / BN)            // 32 N-tiles

// smem layout (dynamic) for GEMM
#define OFF_A 0                                   // STAGES x 16384
#define OFF_B (STAGES * 16384)                    // STAGES x 32768
#define OFF_W2 (OFF_B + STAGES * 32768)           // 196608
#define OFF_PART (OFF_W2 + CDIM * BN * 4)         // 206848
#define SMEM_TOTAL (OFF_PART + BM * CDIM * 4)     // 211968

#define SEL_NB 592                 // co-resident blocks for persistent select

// ---------------- scratch (device globals; no allocation allowed) ----------------
__device__ __half   g_xh[MDIM * KPAD];
__device__ __half   g_w1h[NDIM * KPAD];
__device__ float    g_w2m[CDIM * NDIM];
__device__ float    g_part[NT2 * MDIM * CDIM];
__device__ unsigned g_h1024[1024];
__device__ unsigned g_prefix;
__device__ unsigned g_rank;
__device__ unsigned g_nLess;
__device__ unsigned g_nTie;
__device__ unsigned g_T[2];
__device__ unsigned g_cutoff[2];
__device__ unsigned g_tieIdx[8192];
__device__ unsigned g_bar_cnt;
__device__ unsigned g_bar_gen;

__device__ __forceinline__ unsigned fbits_abs(float v) {
    return __float_as_uint(fabsf(v));
}
__device__ __forceinline__ uint32_t smem_u32(const void* p) {
    uint32_t a;
    asm("{ .reg .u64 t; cvta.to.shared.u64 t, %1; cvt.u32.u64 %0, t; }" : "=r"(a) : "l"(p));
    return a;
}

// ---------------- software grid barrier (all SEL_NB blocks co-resident) ----------------
__device__ __forceinline__ void grid_bar() {
    __syncthreads();
    if (threadIdx.x == 0) {
        unsigned gen = *((volatile unsigned*)&g_bar_gen);
        __threadfence();
        unsigned a = atomicAdd(&g_bar_cnt, 1u);
        if (a == SEL_NB - 1) {
            g_bar_cnt = 0;
            __threadfence();
            atomicAdd(&g_bar_gen, 1u);
        } else {
            while (*((volatile unsigned*)&g_bar_gen) == gen) { }
        }
        __threadfence();
    }
    __syncthreads();
}

// ---------------- fused exact radix select (3 x 10-bit passes + ties) ----------------
// scores |s| < 1 -> abs bits fit in 30 bits.
__global__ void __launch_bounds__(256) k_select(const float* __restrict__ s, int n,
                                                unsigned j, int sel) {
    __shared__ unsigned h[1024];
    __shared__ unsigned sc[256];
    const int tid = threadIdx.x;
    const int gstride = SEL_NB * 256;
    const int gbase = blockIdx.x * 256 + tid;
    const float4* s4 = (const float4*)s;
    const int n4 = n >> 2;

    if (blockIdx.x == 0) {
        for (int b = tid; b < 1024; b += 256) g_h1024[b] = 0u;
        if (tid == 0) { g_prefix = 0u; g_rank = j; g_nLess = 0u; g_nTie = 0u; }
    }
    grid_bar();

    // 3 radix passes: shifts 20, 10, 0
#pragma unroll 1
    for (int pass = 0; pass < 3; pass++) {
        const int shift = 20 - 10 * pass;
        const unsigned prefix = g_prefix;
        for (int b = tid; b < 1024; b += 256) h[b] = 0u;
        __syncthreads();
        for (int i = gbase; i < n4; i += gstride) {
            float4 v = s4[i];
            unsigned b0 = fbits_abs(v.x), b1 = fbits_abs(v.y);
            unsigned b2 = fbits_abs(v.z), b3 = fbits_abs(v.w);
            if (pass == 0) {
                atomicAdd(&h[b0 >> 20], 1u); atomicAdd(&h[b1 >> 20], 1u);
                atomicAdd(&h[b2 >> 20], 1u); atomicAdd(&h[b3 >> 20], 1u);
            } else {
                if (((b0 ^ prefix) >> (shift + 10)) == 0u) atomicAdd(&h[(b0 >> shift) & 1023u], 1u);
                if (((b1 ^ prefix) >> (shift + 10)) == 0u) atomicAdd(&h[(b1 >> shift) & 1023u], 1u);
                if (((b2 ^ prefix) >> (shift + 10)) == 0u) atomicAdd(&h[(b2 >> shift) & 1023u], 1u);
                if (((b3 ^ prefix) >> (shift + 10)) == 0u) atomicAdd(&h[(b3 >> shift) & 1023u], 1u);
            }
        }
        __syncthreads();
        for (int b = tid; b < 1024; b += 256)
            if (h[b]) atomicAdd(&g_h1024[b], h[b]);
        grid_bar();

        if (blockIdx.x == 0) {
            unsigned c0 = g_h1024[4 * tid + 0], c1 = g_h1024[4 * tid + 1];
            unsigned c2 = g_h1024[4 * tid + 2], c3 = g_h1024[4 * tid + 3];
            unsigned mysum = c0 + c1 + c2 + c3;
            sc[tid] = mysum;
            __syncthreads();
#pragma unroll
            for (int off = 1; off < 256; off <<= 1) {
                unsigned v = (tid >= off) ? sc[tid - off] : 0u;
                __syncthreads();
                sc[tid] += v;
                __syncthreads();
            }
            unsigned incl = sc[tid], excl = incl - mysum;
            unsigned r = g_rank;
            if (excl <= r && r < incl) {
                unsigned d, cum = excl;
                if (r < cum + c0) { d = 4 * tid + 0; }
                else if (r < cum + c0 + c1) { d = 4 * tid + 1; cum += c0; }
                else if (r < cum + c0 + c1 + c2) { d = 4 * tid + 2; cum += c0 + c1; }
                else { d = 4 * tid + 3; cum += c0 + c1 + c2; }
                g_prefix = g_prefix | (d << shift);
                g_rank = r - cum;
            }
            __syncthreads();
            for (int b = tid; b < 1024; b += 256) g_h1024[b] = 0u;
            __threadfence();
        }
        grid_bar();
    }

    // tie pass: count below-threshold and gather tie indices
    const unsigned T = g_prefix;
    unsigned nless = 0u;
    for (int i = gbase; i < n; i += gstride) {
        unsigned bits = fbits_abs(s[i]);
        if (bits < T) nless++;
        else if (bits == T) {
            unsigned p = atomicAdd(&g_nTie, 1u);
            if (p < 8192u) g_tieIdx[p] = (unsigned)i;
        }
    }
    sc[tid] = nless;
    __syncthreads();
#pragma unroll
    for (int off = 128; off > 0; off >>= 1) {
        if (tid < off) sc[tid] += sc[tid + off];
        __syncthreads();
    }
    if (tid == 0 && sc[0]) atomicAdd(&g_nLess, sc[0]);
    grid_bar();

    if (blockIdx.x == 0) {
        unsigned nLess = g_nLess;
        unsigned nTie = g_nTie; if (nTie > 8192u) nTie = 8192u;
        unsigned r2 = j - nLess;
        if (tid == 0) {
            g_T[sel] = T;
            if (r2 >= nTie) g_cutoff[sel] = 0xFFFFFFFFu;
        }
        __syncthreads();
        if (r2 < nTie) {
            for (unsigned t = tid; t < nTie; t += 256u) {
                unsigned mi = g_tieIdx[t];
                unsigned cnt = 0;
                for (unsigned u = 0; u < nTie; u++) cnt += (g_tieIdx[u] < mi) ? 1u : 0u;
                if (cnt == r2) g_cutoff[sel] = mi;
            }
        }
    }
}

// ---------------- build masked fp16 weights / convert x to fp16 ----------------
__global__ void k_build_w1h(const float* __restrict__ w1, const float* __restrict__ s1) {
    // one thread per 4 elements of the KPAD layout
    int i = blockIdx.x * blockDim.x + threadIdx.x;
    if (i >= NDIM * (KPAD / 4)) return;
    int row = i / (KPAD / 4), k4 = (i % (KPAD / 4)) * 4;
    __half2 o[2];
    if (k4 < KDIM) {
        int src = row * KDIM + k4;
        float4 w = *(const float4*)(w1 + src);
        float4 sv = *(const float4*)(s1 + src);
        unsigned T = g_T[0], cut = g_cutoff[0];
        unsigned b0 = fbits_abs(sv.x), b1 = fbits_abs(sv.y);
        unsigned b2 = fbits_abs(sv.z), b3 = fbits_abs(sv.w);
        float f0 = ((b0 > T) || (b0 == T && (unsigned)(src + 0) >= cut)) ? w.x : 0.0f;
        float f1 = ((b1 > T) || (b1 == T && (unsigned)(src + 1) >= cut)) ? w.y : 0.0f;
        float f2 = ((b2 > T) || (b2 == T && (unsigned)(src + 2) >= cut)) ? w.z : 0.0f;
        float f3 = ((b3 > T) || (b3 == T && (unsigned)(src + 3) >= cut)) ? w.w : 0.0f;
        o[0] = __floats2half2_rn(f0, f1);
        o[1] = __floats2half2_rn(f2, f3);
    } else {
        o[0] = o[1] = __floats2half2_rn(0.0f, 0.0f);
    }
    *(uint2*)(g_w1h + (size_t)row * KPAD + k4) = *(const uint2*)o;
}

__global__ void k_build_w2m(const float* __restrict__ w2, const float* __restrict__ s2) {
    int i = blockIdx.x * blockDim.x + threadIdx.x;
    if (i >= NK2) return;
    unsigned bits = fbits_abs(s2[i]);
    unsigned T = g_T[1], cut = g_cutoff[1];
    bool keep = (bits > T) || (bits == T && (unsigned)i >= cut);
    g_w2m[i] = keep ? w2[i] : 0.0f;
}

__global__ void k_cvt_xh(const float* __restrict__ x) {
    int i = blockIdx.x * blockDim.x + threadIdx.x;
    if (i >= MDIM * (KPAD / 8)) return;
    int row = i / (KPAD / 8), u = i % (KPAD / 8);
    int c8 = u * 8;
    __half2 h[4];
    if (c8 < KDIM) {
        const float4* p = (const float4*)(x + (size_t)row * KDIM + c8);
        float4 v0 = p[0], v1 = p[1];
        h[0] = __floats2half2_rn(v0.x, v0.y);
        h[1] = __floats2half2_rn(v0.z, v0.w);
        h[2] = __floats2half2_rn(v1.x, v1.y);
        h[3] = __floats2half2_rn(v1.z, v1.w);
    } else {
        h[0] = h[1] = h[2] = h[3] = __floats2half2_rn(0.0f, 0.0f);
    }
    *(uint4*)(g_xh + (size_t)row * KPAD + c8) = *(const uint4*)h;
}

// ---------------- GEMM helpers ----------------
__device__ __forceinline__ void cp16(uint32_t dst, const void* src) {
    asm volatile("cp.async.cg.shared.global [%0], [%1], 16;" :: "r"(dst), "l"(src));
}
#define CP_COMMIT() asm volatile("cp.async.commit_group;" ::: "memory")
#define CP_WAIT(n)  asm volatile("cp.async.wait_group %0;" :: "n"(n) : "memory")

__device__ __forceinline__ void ldsm4(unsigned& r0, unsigned& r1, unsigned& r2, unsigned& r3,
                                      uint32_t addr) {
    asm volatile("ldmatrix.sync.aligned.m8n8.x4.shared.b16 {%0,%1,%2,%3}, [%4];"
                 : "=r"(r0), "=r"(r1), "=r"(r2), "=r"(r3) : "r"(addr));
}

__device__ __forceinline__ void mma_fp16(float* d, const unsigned* a, const unsigned* b) {
    asm volatile(
        "mma.sync.aligned.m16n8k16.row.col.f32.f16.f16.f32 "
        "{%0,%1,%2,%3}, {%4,%5,%6,%7}, {%8,%9}, {%0,%1,%2,%3};\n"
        : "+f"(d[0]), "+f"(d[1]), "+f"(d[2]), "+f"(d[3])
        : "r"(a[0]), "r"(a[1]), "r"(a[2]), "r"(a[3]), "r"(b[0]), "r"(b[1]));
}

__device__ __forceinline__ uint32_t sw_off(uint32_t row, uint32_t u) {
    return row * 128u + ((u ^ (row & 7u)) << 4);
}

// ---------------- GEMM1 (fp16 mma.sync, 64x64 warp tiles) + fused relu/w2 epilogue ----------------
__global__ void __launch_bounds__(256, 1) k_gemm1() {
    extern __shared__ __align__(1024) char smem[];
    const uint32_t sb = smem_u32(smem);
    const int tid = threadIdx.x;
    const int nt = blockIdx.x;
    const int mt = blockIdx.y;

    const int wid = tid >> 5, lane = tid & 31;
    const int mw = wid & 1;
    const int nw = wid >> 1;
    const int g4 = lane >> 2, t4 = lane & 3;
    const int r8 = lane & 7;

    float* W2s  = (float*)(smem + OFF_W2);
    float* Part = (float*)(smem + OFF_PART);
    for (int p = tid; p < CDIM * BN; p += 256)
        W2s[p] = g_w2m[(p >> 8) * NDIM + nt * BN + (p & 255)];
    for (int p = tid; p < BM * CDIM; p += 256)
        Part[p] = 0.0f;

    const char* Ag = (const char*)(g_xh  + (size_t)(mt * BM) * KPAD);
    const char* Bg = (const char*)(g_w1h + (size_t)(nt * BN) * KPAD);
    const size_t rowBytes = KPAD * 2;

    const uint32_t aRowL = (uint32_t)(mw * 64 + ((lane >> 3) & 1) * 8 + r8);
    const uint32_t uA    = (uint32_t)(lane >> 4);
    const uint32_t bRowL = (uint32_t)(nw * 64 + (lane >> 4) * 8 + r8);
    const uint32_t uB    = (uint32_t)((lane >> 3) & 1);

    float d[4][8][4];
#pragma unroll
    for (int i = 0; i < 4; i++)
#pragma unroll
        for (int j = 0; j < 8; j++)
#pragma unroll
            for (int r = 0; r < 4; r++) d[i][j][r] = 0.0f;

#define ISSUE_STAGE(st) do {                                                      \
    const int _s = (st) & (STAGES - 1);                                           \
    const char* _ab = Ag + (size_t)(st) * 128;                                    \
    const char* _bb = Bg + (size_t)(st) * 128;                                    \
    _Pragma("unroll")                                                             \
    for (int q = 0; q < 4; q++) {                                                 \
        int idx = tid + q * 256;                                                  \
        uint32_t row = (uint32_t)(idx >> 3), u = (uint32_t)(idx & 7);             \
        cp16(sb + OFF_A + _s * 16384 + sw_off(row, u),                            \
             _ab + (size_t)row * rowBytes + u * 16);                              \
    }                                                                             \
    _Pragma("unroll")                                                             \
    for (int q = 0; q < 8; q++) {                                                 \
        int idx = tid + q * 256;                                                  \
        uint32_t row = (uint32_t)(idx >> 3), u = (uint32_t)(idx & 7);             \
        cp16(sb + OFF_B + _s * 32768 + sw_off(row, u),                            \
             _bb + (size_t)row * rowBytes + u * 16);                              \
    }                                                                             \
} while (0)

    ISSUE_STAGE(0); CP_COMMIT();
    ISSUE_STAGE(1); CP_COMMIT();
    ISSUE_STAGE(2); CP_COMMIT();

    for (int kk = 0; kk < NITER; kk++) {
        CP_WAIT(2);
        __syncthreads();
        // issue next stage FIRST so its gmem loads overlap this stage's MMAs
        const int nx = kk + 3;
        if (nx < NITER) { ISSUE_STAGE(nx); CP_COMMIT(); }

        const uint32_t aB = sb + OFF_A + (kk & 3) * 16384;
        const uint32_t bB = sb + OFF_B + (kk & 3) * 32768;
#pragma unroll
        for (int ks = 0; ks < 4; ks++) {
            const uint32_t ul = (uint32_t)(2 * ks);
            unsigned A4[4][4], B4[4][4];
#pragma unroll
            for (int i = 0; i < 4; i++) {
                uint32_t row = aRowL + (uint32_t)(i * 16);
                ldsm4(A4[i][0], A4[i][1], A4[i][2], A4[i][3],
                      aB + sw_off(row, ul + uA));
            }
#pragma unroll
            for (int j2 = 0; j2 < 4; j2++) {
                uint32_t row = bRowL + (uint32_t)(j2 * 16);
                ldsm4(B4[j2][0], B4[j2][1], B4[j2][2], B4[j2][3],
                      bB + sw_off(row, ul + uB));
            }
#pragma unroll
            for (int i = 0; i < 4; i++)
#pragma unroll
                for (int j = 0; j < 8; j++)
                    mma_fp16(d[i][j], A4[i], &B4[j >> 1][2 * (j & 1)]);
        }
    }

    // ---- epilogue: relu + contract with w2 slice ----
#pragma unroll
    for (int i = 0; i < 4; i++) {
#pragma unroll
        for (int h = 0; h < 2; h++) {
            const int row = mw * 64 + i * 16 + g4 + h * 8;
            float v0[8], v1[8];
#pragma unroll
            for (int j = 0; j < 8; j++) {
                v0[j] = fmaxf(d[i][j][2 * h + 0], 0.0f);
                v1[j] = fmaxf(d[i][j][2 * h + 1], 0.0f);
            }
#pragma unroll
            for (int c = 0; c < CDIM; c++) {
                float s = 0.0f;
#pragma unroll
                for (int j = 0; j < 8; j++) {
                    float2 w = *(const float2*)&W2s[c * BN + nw * 64 + j * 8 + 2 * t4];
                    s += v0[j] * w.x + v1[j] * w.y;
                }
                s += __shfl_xor_sync(0xFFFFFFFFu, s, 1);
                s += __shfl_xor_sync(0xFFFFFFFFu, s, 2);
                if (t4 == 0) atomicAdd(&Part[row * CDIM + c], s);
            }
        }
    }
    __syncthreads();

    float* outp = g_part + (size_t)nt * (MDIM * CDIM) + (size_t)(mt * BM) * CDIM;
    for (int p = tid; p < BM * CDIM; p += 256) outp[p] = Part[p];
#undef ISSUE_STAGE
}

// ---------------- reduce partials + log_softmax ----------------
__global__ void k_reduce(float* __restrict__ out) {   // <<<512, 320>>>
    const int tid = threadIdx.x;
    const int base = blockIdx.x * 32 * CDIM;
    float s = 0.0f;
#pragma unroll 8
    for (int nt = 0; nt < NT2; nt++)
        s += g_part[(size_t)nt * (MDIM * CDIM) + base + tid];
    __shared__ float L[32 * CDIM];
    L[tid] = s;
    __syncthreads();
    const int rl = tid / CDIM;
    float m = -INFINITY;
#pragma unroll
    for (int c = 0; c < CDIM; c++) m = fmaxf(m, L[rl * CDIM + c]);
    float se = 0.0f;
#pragma unroll
    for (int c = 0; c < CDIM; c++) se += expf(L[rl * CDIM + c] - m);
    out[base + tid] = s - m - logf(se);
}

// ---------------- launch ----------------
extern "C" void kernel_launch(void* const* d_in, const int* in_sizes, int n_in,
                              void* d_out, int out_size) {
    const float* x  = (const float*)d_in[0];
    const float* w1 = (const float*)d_in[1];
    const float* s1 = (const float*)d_in[2];
    const float* w2 = (const float*)d_in[3];
    const float* s2 = (const float*)d_in[4];
    float* out = (float*)d_out;

    cudaFuncSetAttribute(k_gemm1, cudaFuncAttributeMaxDynamicSharedMemorySize, SMEM_TOTAL);

    // launch order is load-bearing: k_gemm1 must be launch index 5 so ncu (-s 5 -c 1)
    // profiles the GEMM.
    k_select<<<SEL_NB, 256>>>(s1, NK1, J1, 0);                       // 0
    k_select<<<SEL_NB, 256>>>(s2, NK2, J2, 1);                       // 1
    k_build_w1h<<<(NDIM * (KPAD / 4) + 255) / 256, 256>>>(w1, s1);   // 2
    k_build_w2m<<<(NK2 + 255) / 256, 256>>>(w2, s2);                 // 3
    k_cvt_xh<<<(MDIM * (KPAD / 8) + 255) / 256, 256>>>(x);           // 4
    dim3 grid(NT2, MDIM / BM);
    k_gemm1<<<grid, 256, SMEM_TOTAL>>>();                            // 5  <- ncu target
    k_reduce<<<MDIM / 32, 32 * CDIM>>>(out);                         // 6
}